// round 10
// baseline (speedup 1.0000x reference)
#include <cuda_runtime.h>
#include <cuda_bf16.h>

#define N_NODES 100000
#define N_EDGES 3200000
#define IN_CH   256

// Scratch (device globals: allocation APIs are forbidden)
__device__ float g_xm[N_NODES];    // x @ W_mlp
__device__ float g_xl[N_NODES];    // x @ W_lin
__device__ float g_xw[N_NODES];    // x @ W_gcn
__device__ float g_degf[N_NODES];  // in-degree (float)
__device__ float g_h[N_NODES];     // rsqrt(deg+1) * xw
__device__ float g_gcn[N_NODES];   // accumulates sum_s h[s]

#define DOT_BLOCKS 592
#define DOT_WARPS  (DOT_BLOCKS * 8)        // 4736
#define EGROUPS    (N_EDGES / 8)           // 400000 (8 edges per thread)
#define EDG_BLOCKS ((EGROUPS + 255) / 256) // 1563

// Streams/events created once at static init (driver objects, not device mem).
struct SideStreams {
    cudaStream_t s1, s2;
    cudaEvent_t  evFork, evDeg, evXW, evXML;
    SideStreams() {
        cudaStreamCreateWithFlags(&s1, cudaStreamNonBlocking);
        cudaStreamCreateWithFlags(&s2, cudaStreamNonBlocking);
        cudaEventCreateWithFlags(&evFork, cudaEventDisableTiming);
        cudaEventCreateWithFlags(&evDeg,  cudaEventDisableTiming);
        cudaEventCreateWithFlags(&evXW,   cudaEventDisableTiming);
        cudaEventCreateWithFlags(&evXML,  cudaEventDisableTiming);
    }
};
static SideStreams g_ss;

// ---------------------------------------------------------------------------
// xw_dot: only the W_gcn dot (the one msg depends on). Warp/node, 4-node ILP.
__global__ void __launch_bounds__(256) xw_dot_kernel(
        const float* __restrict__ x,
        const float* __restrict__ Wg) {
    int wid  = (blockIdx.x * 256 + threadIdx.x) >> 5;
    int lane = threadIdx.x & 31;
    int i0 = lane, i1 = lane + 32;

    const float4* wg4 = (const float4*)Wg;
    float4 g0 = __ldg(&wg4[i0]), g1 = __ldg(&wg4[i1]);

    const int stride = DOT_WARPS;
    for (int n0 = wid; n0 < N_NODES; n0 += 4 * stride) {
        int n1 = n0 + stride, n2 = n0 + 2 * stride, n3 = n0 + 3 * stride;
        bool h1 = n1 < N_NODES, h2 = n2 < N_NODES, h3 = n3 < N_NODES;

        const float4* x0 = (const float4*)(x + (size_t)n0 * IN_CH);
        const float4* x1 = (const float4*)(x + (size_t)(h1 ? n1 : n0) * IN_CH);
        const float4* x2 = (const float4*)(x + (size_t)(h2 ? n2 : n0) * IN_CH);
        const float4* x3 = (const float4*)(x + (size_t)(h3 ? n3 : n0) * IN_CH);

        float4 a0 = x0[i0], a1 = x0[i1];
        float4 b0 = x1[i0], b1 = x1[i1];
        float4 c0 = x2[i0], c1 = x2[i1];
        float4 d0 = x3[i0], d1 = x3[i1];

        float sA = a0.x*g0.x + a0.y*g0.y + a0.z*g0.z + a0.w*g0.w
                 + a1.x*g1.x + a1.y*g1.y + a1.z*g1.z + a1.w*g1.w;
        float sB = b0.x*g0.x + b0.y*g0.y + b0.z*g0.z + b0.w*g0.w
                 + b1.x*g1.x + b1.y*g1.y + b1.z*g1.z + b1.w*g1.w;
        float sC = c0.x*g0.x + c0.y*g0.y + c0.z*g0.z + c0.w*g0.w
                 + c1.x*g1.x + c1.y*g1.y + c1.z*g1.z + c1.w*g1.w;
        float sD = d0.x*g0.x + d0.y*g0.y + d0.z*g0.z + d0.w*g0.w
                 + d1.x*g1.x + d1.y*g1.y + d1.z*g1.z + d1.w*g1.w;

#pragma unroll
        for (int o = 16; o > 0; o >>= 1) {
            sA += __shfl_xor_sync(0xffffffffu, sA, o);
            sB += __shfl_xor_sync(0xffffffffu, sB, o);
            sC += __shfl_xor_sync(0xffffffffu, sC, o);
            sD += __shfl_xor_sync(0xffffffffu, sD, o);
        }
        if (lane == 0) {
            g_xw[n0] = sA;
            if (h1) g_xw[n1] = sB;
            if (h2) g_xw[n2] = sC;
            if (h3) g_xw[n3] = sD;
        }
    }
}

// ---------------------------------------------------------------------------
// xml_dot: the W_mlp and W_lin dots (only needed by final) — runs on a side
// stream concurrently with h+msg.
__global__ void __launch_bounds__(256) xml_dot_kernel(
        const float* __restrict__ x,
        const float* __restrict__ Wm,
        const float* __restrict__ Wl) {
    int wid  = (blockIdx.x * 256 + threadIdx.x) >> 5;
    int lane = threadIdx.x & 31;
    int i0 = lane, i1 = lane + 32;

    const float4* wm4 = (const float4*)Wm;
    const float4* wl4 = (const float4*)Wl;
    float4 m0 = __ldg(&wm4[i0]), m1 = __ldg(&wm4[i1]);
    float4 l0 = __ldg(&wl4[i0]), l1 = __ldg(&wl4[i1]);

    const int stride = DOT_WARPS;
    for (int n0 = wid; n0 < N_NODES; n0 += 4 * stride) {
        int n1 = n0 + stride, n2 = n0 + 2 * stride, n3 = n0 + 3 * stride;
        bool h1 = n1 < N_NODES, h2 = n2 < N_NODES, h3 = n3 < N_NODES;

        const float4* x0 = (const float4*)(x + (size_t)n0 * IN_CH);
        const float4* x1 = (const float4*)(x + (size_t)(h1 ? n1 : n0) * IN_CH);
        const float4* x2 = (const float4*)(x + (size_t)(h2 ? n2 : n0) * IN_CH);
        const float4* x3 = (const float4*)(x + (size_t)(h3 ? n3 : n0) * IN_CH);

        float4 a0 = x0[i0], a1 = x0[i1];
        float4 b0 = x1[i0], b1 = x1[i1];
        float4 c0 = x2[i0], c1 = x2[i1];
        float4 d0 = x3[i0], d1 = x3[i1];

        float smA = a0.x*m0.x + a0.y*m0.y + a0.z*m0.z + a0.w*m0.w
                  + a1.x*m1.x + a1.y*m1.y + a1.z*m1.z + a1.w*m1.w;
        float slA = a0.x*l0.x + a0.y*l0.y + a0.z*l0.z + a0.w*l0.w
                  + a1.x*l1.x + a1.y*l1.y + a1.z*l1.z + a1.w*l1.w;
        float smB = b0.x*m0.x + b0.y*m0.y + b0.z*m0.z + b0.w*m0.w
                  + b1.x*m1.x + b1.y*m1.y + b1.z*m1.z + b1.w*m1.w;
        float slB = b0.x*l0.x + b0.y*l0.y + b0.z*l0.z + b0.w*l0.w
                  + b1.x*l1.x + b1.y*l1.y + b1.z*l1.z + b1.w*l1.w;
        float smC = c0.x*m0.x + c0.y*m0.y + c0.z*m0.z + c0.w*m0.w
                  + c1.x*m1.x + c1.y*m1.y + c1.z*m1.z + c1.w*m1.w;
        float slC = c0.x*l0.x + c0.y*l0.y + c0.z*l0.z + c0.w*l0.w
                  + c1.x*l1.x + c1.y*l1.y + c1.z*l1.z + c1.w*l1.w;
        float smD = d0.x*m0.x + d0.y*m0.y + d0.z*m0.z + d0.w*m0.w
                  + d1.x*m1.x + d1.y*m1.y + d1.z*m1.z + d1.w*m1.w;
        float slD = d0.x*l0.x + d0.y*l0.y + d0.z*l0.z + d0.w*l0.w
                  + d1.x*l1.x + d1.y*l1.y + d1.z*l1.z + d1.w*l1.w;

#pragma unroll
        for (int o = 16; o > 0; o >>= 1) {
            smA += __shfl_xor_sync(0xffffffffu, smA, o);
            slA += __shfl_xor_sync(0xffffffffu, slA, o);
            smB += __shfl_xor_sync(0xffffffffu, smB, o);
            slB += __shfl_xor_sync(0xffffffffu, slB, o);
            smC += __shfl_xor_sync(0xffffffffu, smC, o);
            slC += __shfl_xor_sync(0xffffffffu, slC, o);
            smD += __shfl_xor_sync(0xffffffffu, smD, o);
            slD += __shfl_xor_sync(0xffffffffu, slD, o);
        }
        if (lane == 0) {
            g_xm[n0] = smA; g_xl[n0] = slA;
            if (h1) { g_xm[n1] = smB; g_xl[n1] = slB; }
            if (h2) { g_xm[n2] = smC; g_xl[n2] = slC; }
            if (h3) { g_xm[n3] = smD; g_xl[n3] = slD; }
        }
    }
}

// ---------------------------------------------------------------------------
// Degree count: 8 edges/thread (runs on side stream 1, parallel with xw_dot).
__global__ void __launch_bounds__(256) deg_kernel(const int* __restrict__ dst) {
    int t = blockIdx.x * 256 + threadIdx.x;
    if (t >= EGROUPS) return;
    const int4* d4p = (const int4*)dst;
    int4 a = d4p[t];
    int4 b = d4p[t + EGROUPS];
    atomicAdd(&g_degf[a.x], 1.0f);
    atomicAdd(&g_degf[a.y], 1.0f);
    atomicAdd(&g_degf[a.z], 1.0f);
    atomicAdd(&g_degf[a.w], 1.0f);
    atomicAdd(&g_degf[b.x], 1.0f);
    atomicAdd(&g_degf[b.y], 1.0f);
    atomicAdd(&g_degf[b.z], 1.0f);
    atomicAdd(&g_degf[b.w], 1.0f);
}

// ---------------------------------------------------------------------------
// h[n] = rsqrt(deg+1) * xw[n], 4 nodes/thread (N_NODES % 4 == 0).
__global__ void __launch_bounds__(256) h_kernel() {
    int i = blockIdx.x * 256 + threadIdx.x;
    if (i < N_NODES / 4) {
        float4 d = ((const float4*)g_degf)[i];
        float4 w = ((const float4*)g_xw)[i];
        float4 r;
        r.x = rsqrtf(d.x + 1.0f) * w.x;
        r.y = rsqrtf(d.y + 1.0f) * w.y;
        r.z = rsqrtf(d.z + 1.0f) * w.z;
        r.w = rsqrtf(d.w + 1.0f) * w.w;
        ((float4*)g_h)[i] = r;
    }
}

// ---------------------------------------------------------------------------
// Edge messages: gcn[d] += h[s]. 8 edges/thread, gathers batched.
__global__ void __launch_bounds__(256) msg_kernel(const int* __restrict__ src,
                                                  const int* __restrict__ dst) {
    int t = blockIdx.x * 256 + threadIdx.x;
    if (t >= EGROUPS) return;
    const int4* s4p = (const int4*)src;
    const int4* d4p = (const int4*)dst;
    int4 sa = s4p[t];
    int4 sb = s4p[t + EGROUPS];
    int4 da = d4p[t];
    int4 db = d4p[t + EGROUPS];

    float h0 = __ldg(&g_h[sa.x]);
    float h1 = __ldg(&g_h[sa.y]);
    float h2 = __ldg(&g_h[sa.z]);
    float h3 = __ldg(&g_h[sa.w]);
    float h4 = __ldg(&g_h[sb.x]);
    float h5 = __ldg(&g_h[sb.y]);
    float h6 = __ldg(&g_h[sb.z]);
    float h7 = __ldg(&g_h[sb.w]);

    atomicAdd(&g_gcn[da.x], h0);
    atomicAdd(&g_gcn[da.y], h1);
    atomicAdd(&g_gcn[da.z], h2);
    atomicAdd(&g_gcn[da.w], h3);
    atomicAdd(&g_gcn[db.x], h4);
    atomicAdd(&g_gcn[db.y], h5);
    atomicAdd(&g_gcn[db.z], h6);
    atomicAdd(&g_gcn[db.w], h7);
}

// ---------------------------------------------------------------------------
__device__ __forceinline__ float fsigmoid(float v) {
    return 1.0f / (1.0f + __expf(-v));
}

__device__ __forceinline__ float fitness1(float degf, float xm, float xl,
                                          float gcnacc, float hv,
                                          float alpha, float beta,
                                          const float* W_att, const float* b_att) {
    float dinv = rsqrtf(degf + 1.0f);
    float gcn  = dinv * (gcnacc + hv);      // h = dinv*xw
    float s1 = fsigmoid(alpha * sqrtf(degf) + beta);
    float s2 = fsigmoid(xm);
    float s3 = fsigmoid(gcn + xl);
    float l0 = s1 * __ldg(&W_att[0]) + s2 * __ldg(&W_att[1]) + s3 * __ldg(&W_att[2]) + __ldg(&b_att[0]);
    float l1 = s1 * __ldg(&W_att[3]) + s2 * __ldg(&W_att[4]) + s3 * __ldg(&W_att[5]) + __ldg(&b_att[1]);
    float l2 = s1 * __ldg(&W_att[6]) + s2 * __ldg(&W_att[7]) + s3 * __ldg(&W_att[8]) + __ldg(&b_att[2]);
    float m  = fmaxf(l0, fmaxf(l1, l2));
    float e0 = __expf(l0 - m), e1 = __expf(l1 - m), e2 = __expf(l2 - m);
    float inv = 1.0f / (e0 + e1 + e2);
    return (e0 * s1 + e1 * s2 + e2 * s3) * inv;
}

// Final fusion, 2 nodes/thread (N_NODES even).
__global__ void __launch_bounds__(256) final_kernel(
        const float* __restrict__ alpha_p,
        const float* __restrict__ beta_p,
        const float* __restrict__ W_att,
        const float* __restrict__ b_att,
        float* __restrict__ out) {
    int i = blockIdx.x * 256 + threadIdx.x;
    if (i >= N_NODES / 2) return;

    float alpha = __ldg(alpha_p);
    float beta  = __ldg(beta_p);

    float2 dg = ((const float2*)g_degf)[i];
    float2 xm = ((const float2*)g_xm)[i];
    float2 xl = ((const float2*)g_xl)[i];
    float2 gc = ((const float2*)g_gcn)[i];
    float2 hv = ((const float2*)g_h)[i];

    float2 r;
    r.x = fitness1(dg.x, xm.x, xl.x, gc.x, hv.x, alpha, beta, W_att, b_att);
    r.y = fitness1(dg.y, xm.y, xl.y, gc.y, hv.y, alpha, beta, W_att, b_att);
    ((float2*)out)[i] = r;
}

// ---------------------------------------------------------------------------
extern "C" void kernel_launch(void* const* d_in, const int* in_sizes, int n_in,
                              void* d_out, int out_size) {
    const float* x     = (const float*)d_in[0];
    const int*   eidx  = (const int*)d_in[1];   // [2, N_EDGES] int32
    const float* alpha = (const float*)d_in[2];
    const float* beta  = (const float*)d_in[3];
    const float* Wm    = (const float*)d_in[4];
    const float* Wl    = (const float*)d_in[5];
    const float* Wg    = (const float*)d_in[6];
    const float* Watt  = (const float*)d_in[7];
    const float* batt  = (const float*)d_in[8];
    float* out = (float*)d_out;

    const int* src = eidx;            // edge_index[0]
    const int* dst = eidx + N_EDGES;  // edge_index[1]

    void *degf_ptr = nullptr, *gcn_ptr = nullptr;
    cudaGetSymbolAddress(&degf_ptr, g_degf);
    cudaGetSymbolAddress(&gcn_ptr,  g_gcn);
    cudaMemsetAsync(degf_ptr, 0, N_NODES * sizeof(float), 0);
    cudaMemsetAsync(gcn_ptr,  0, N_NODES * sizeof(float), 0);

    // Fork: deg on s1 (after memsets), concurrent with xw_dot on main.
    cudaEventRecord(g_ss.evFork, 0);
    cudaStreamWaitEvent(g_ss.s1, g_ss.evFork, 0);
    deg_kernel<<<EDG_BLOCKS, 256, 0, g_ss.s1>>>(dst);
    cudaEventRecord(g_ss.evDeg, g_ss.s1);

    xw_dot_kernel<<<DOT_BLOCKS, 256>>>(x, Wg);
    cudaEventRecord(g_ss.evXW, 0);

    // xml_dot on s2: starts after xw_dot, overlaps h + msg.
    cudaStreamWaitEvent(g_ss.s2, g_ss.evXW, 0);
    xml_dot_kernel<<<DOT_BLOCKS, 256, 0, g_ss.s2>>>(x, Wm, Wl);
    cudaEventRecord(g_ss.evXML, g_ss.s2);

    // Main: h (needs deg + xw), then msg.
    cudaStreamWaitEvent(0, g_ss.evDeg, 0);
    h_kernel<<<(N_NODES / 4 + 255) / 256, 256>>>();
    msg_kernel<<<EDG_BLOCKS, 256>>>(src, dst);

    // Final needs xm/xl too.
    cudaStreamWaitEvent(0, g_ss.evXML, 0);
    final_kernel<<<(N_NODES / 2 + 255) / 256, 256>>>(alpha, beta, Watt, batt, out);
}